// round 12
// baseline (speedup 1.0000x reference)
#include <cuda_runtime.h>
#include <cuda_bf16.h>
#include <cstdint>

typedef unsigned int u32;

#define BB 2
#define SS 2048
#define DD 1024
#define HH 16
#define HD 64
#define MM 4096
#define LOG2E 1.4426950408889634f

__device__ float g_q[MM * DD];
__device__ float g_k[MM * DD];
__device__ float g_v[MM * DD];
__device__ float g_attn[MM * DD];
__device__ float g_mask[BB * SS];
__device__ int   g_maskflag;

// ---------------------------------------------------------------------------
// Mask detect / repack (proven)
// ---------------------------------------------------------------------------
__global__ void detect_mask_kernel(const unsigned char* __restrict__ p) {
    __shared__ int f1, f23, f4;
    int tid = threadIdx.x;
    if (tid == 0) { f1 = 0; f23 = 0; f4 = 0; }
    __syncthreads();
    int l1 = 0, l23 = 0, l4 = 0;
    for (int i = tid; i < BB * SS; i += blockDim.x) {
        unsigned char v = p[i];
        if (v) {
            int r = i & 3;
            if (r == 1) l1 = 1;
            else if (r == 2 || r == 3) l23 = 1;
            if ((i & 7) == 4) l4 = 1;
        }
    }
    if (l1)  atomicOr(&f1, 1);
    if (l23) atomicOr(&f23, 1);
    if (l4)  atomicOr(&f4, 1);
    __syncthreads();
    if (tid == 0) {
        int flag;
        if (f1) flag = 0;
        else if (f23) flag = 2;
        else if (f4) flag = 1;
        else flag = 3;
        g_maskflag = flag;
    }
}

__global__ void repack_mask_kernel(const void* __restrict__ p) {
    int i = blockIdx.x * blockDim.x + threadIdx.x;
    if (i >= BB * SS) return;
    int flag = g_maskflag;
    bool mv;
    if (flag == 0)      mv = ((const unsigned char*)p)[i] != 0;
    else if (flag == 1) mv = ((const int*)p)[i] != 0;
    else if (flag == 2) mv = ((const float*)p)[i] != 0.0f;
    else                mv = ((const long long*)p)[i] != 0;
    g_mask[i] = mv ? -1.0e9f : 0.0f;
}

// ---------------------------------------------------------------------------
// bf16 helpers
// ---------------------------------------------------------------------------
__device__ __forceinline__ void bsplit(float a, float b, u32& h, u32& l) {
    __nv_bfloat162 hh = __floats2bfloat162_rn(a, b);
    float ra_ = a - __bfloat162float(hh.x);
    float rb_ = b - __bfloat162float(hh.y);
    __nv_bfloat162 ll = __floats2bfloat162_rn(ra_, rb_);
    h = *(u32*)&hh; l = *(u32*)&ll;
}
__device__ __forceinline__ void mma16(float* c, const u32* a, const u32* b) {
    asm volatile("mma.sync.aligned.m16n8k16.row.col.f32.bf16.bf16.f32 "
        "{%0,%1,%2,%3}, {%4,%5,%6,%7}, {%8,%9}, {%0,%1,%2,%3};"
        : "+f"(c[0]), "+f"(c[1]), "+f"(c[2]), "+f"(c[3])
        : "r"(a[0]), "r"(a[1]), "r"(a[2]), "r"(a[3]), "r"(b[0]), "r"(b[1]));
}
__device__ __forceinline__ void sts2(u32* base, u32 a, u32 b) {
    asm volatile("st.shared.v2.b32 [%0], {%1,%2};"
        :: "l"(__cvta_generic_to_shared(base)), "r"(a), "r"(b) : "memory");
}
__device__ __forceinline__ void sts4(u32* base, u32 a, u32 b, u32 c, u32 d) {
    asm volatile("st.shared.v4.b32 [%0], {%1,%2,%3,%4};"
        :: "l"(__cvta_generic_to_shared(base)), "r"(a), "r"(b), "r"(c), "r"(d) : "memory");
}

// ---------------------------------------------------------------------------
// Split-BF16 GEMM (NT), double-buffered smem pipeline.
// mode 0: QKV fused — blockIdx.z selects (W,b) and dst g_q/g_k/g_v, A = A0.
// mode 1: out proj — A = g_attn, W=W0/b0, C = Cout plain [M,N].
// Per iter: STS(tile k+1) + LDG(tile k+2) overlap MMA(tile k); ONE sync.
// ---------------------------------------------------------------------------
#define SRU 20
#define TU (128 * SRU)                 // 2560 u32 per tile
#define GSM_U32 (8 * TU)               // 2 bufs x 4 tiles
#define GSM_BYTES (GSM_U32 * 4)        // 81920

__global__ __launch_bounds__(256, 1)
void gemm_mma(const float* __restrict__ A0,
              const float* __restrict__ W0, const float* __restrict__ b0p,
              const float* __restrict__ W1, const float* __restrict__ b1p,
              const float* __restrict__ W2, const float* __restrict__ b2p,
              float* __restrict__ Cout, int mode)
{
    extern __shared__ u32 sm[];

    int z = (mode == 0) ? (int)blockIdx.z : 0;
    const float* A = (mode == 0) ? A0 : g_attn;
    const float* W = (z == 0) ? W0 : (z == 1 ? W1 : W2);
    const float* bias = (z == 0) ? b0p : (z == 1 ? b1p : b2p);
    float* C = mode ? Cout : (z == 0 ? g_q : (z == 1 ? g_k : g_v));
    int permute = (mode == 0);

    int tid = threadIdx.x, wid = tid >> 5, lane = tid & 31;
    int gid = lane >> 2, tig = lane & 3;
    int m0 = (int)blockIdx.y << 7, n0 = (int)blockIdx.x << 7;
    int wm = (wid & 3) * 32, wn = (wid >> 2) * 64;

    const float* pA = A + (size_t)(m0 + (tid >> 3)) * DD + (tid & 7) * 4;
    const float* pB = W + (size_t)(n0 + (tid >> 3)) * DD + (tid & 7) * 4;
    int sbase = (tid >> 3) * SRU + (tid & 7) * 2;

    float acc[2][8][4];
#pragma unroll
    for (int mt = 0; mt < 2; mt++)
#pragma unroll
        for (int nt = 0; nt < 8; nt++)
#pragma unroll
            for (int i = 0; i < 4; i++) acc[mt][nt][i] = 0.0f;

    float4 ra[4], rb[4];

    // prologue: tile 0 -> buf0; tile 1 -> regs
#pragma unroll
    for (int j = 0; j < 4; j++) {
        ra[j] = *(const float4*)(pA + (size_t)j * 32 * DD);
        rb[j] = *(const float4*)(pB + (size_t)j * 32 * DD);
    }
    {
        u32* dAh = sm; u32* dAl = sm + TU; u32* dBh = sm + 2 * TU; u32* dBl = sm + 3 * TU;
#pragma unroll
        for (int j = 0; j < 4; j++) {
            int off = sbase + j * 32 * SRU;
            u32 h0, l0, h1, l1;
            bsplit(ra[j].x, ra[j].y, h0, l0);
            bsplit(ra[j].z, ra[j].w, h1, l1);
            sts2(dAh + off, h0, h1); sts2(dAl + off, l0, l1);
            bsplit(rb[j].x, rb[j].y, h0, l0);
            bsplit(rb[j].z, rb[j].w, h1, l1);
            sts2(dBh + off, h0, h1); sts2(dBl + off, l0, l1);
        }
    }
#pragma unroll
    for (int j = 0; j < 4; j++) {
        ra[j] = *(const float4*)(pA + (size_t)j * 32 * DD + 32);
        rb[j] = *(const float4*)(pB + (size_t)j * 32 * DD + 32);
    }
    __syncthreads();

    const int nk = DD / 32;
    for (int kt = 0; kt < nk; kt++) {
        int cur = kt & 1, nxt = cur ^ 1;
        u32* base_c = sm + cur * 4 * TU;

        // STS tile kt+1 into other buffer (regs from last LDG)
        if (kt + 1 < nk) {
            u32* dAh = sm + nxt * 4 * TU; u32* dAl = dAh + TU;
            u32* dBh = dAh + 2 * TU;      u32* dBl = dAh + 3 * TU;
#pragma unroll
            for (int j = 0; j < 4; j++) {
                int off = sbase + j * 32 * SRU;
                u32 h0, l0, h1, l1;
                bsplit(ra[j].x, ra[j].y, h0, l0);
                bsplit(ra[j].z, ra[j].w, h1, l1);
                sts2(dAh + off, h0, h1); sts2(dAl + off, l0, l1);
                bsplit(rb[j].x, rb[j].y, h0, l0);
                bsplit(rb[j].z, rb[j].w, h1, l1);
                sts2(dBh + off, h0, h1); sts2(dBl + off, l0, l1);
            }
        }
        // LDG tile kt+2
        if (kt + 2 < nk) {
#pragma unroll
            for (int j = 0; j < 4; j++) {
                ra[j] = *(const float4*)(pA + (size_t)j * 32 * DD + (kt + 2) * 32);
                rb[j] = *(const float4*)(pB + (size_t)j * 32 * DD + (kt + 2) * 32);
            }
        }

        // MMA on current buffer
        u32* sAh = base_c;          u32* sAl = base_c + TU;
        u32* sBh = base_c + 2 * TU; u32* sBl = base_c + 3 * TU;
#pragma unroll
        for (int ks = 0; ks < 2; ks++) {
            int ko = ks * 8;
            u32 ah[2][4], al[2][4];
#pragma unroll
            for (int mt = 0; mt < 2; mt++) {
                int base = (wm + mt * 16 + gid) * SRU + ko + tig;
                ah[mt][0] = sAh[base];
                ah[mt][1] = sAh[base + 8 * SRU];
                ah[mt][2] = sAh[base + 4];
                ah[mt][3] = sAh[base + 8 * SRU + 4];
                al[mt][0] = sAl[base];
                al[mt][1] = sAl[base + 8 * SRU];
                al[mt][2] = sAl[base + 4];
                al[mt][3] = sAl[base + 8 * SRU + 4];
            }
            u32 bh[8][2], bl[8][2];
#pragma unroll
            for (int nt = 0; nt < 8; nt++) {
                int base = (wn + nt * 8 + gid) * SRU + ko + tig;
                bh[nt][0] = sBh[base];
                bh[nt][1] = sBh[base + 4];
                bl[nt][0] = sBl[base];
                bl[nt][1] = sBl[base + 4];
            }
#pragma unroll
            for (int mt = 0; mt < 2; mt++)
#pragma unroll
                for (int nt = 0; nt < 8; nt++) {
                    mma16(acc[mt][nt], ah[mt], bh[nt]);
                    mma16(acc[mt][nt], ah[mt], bl[nt]);
                    mma16(acc[mt][nt], al[mt], bh[nt]);
                }
        }
        __syncthreads();
    }

#pragma unroll
    for (int mt = 0; mt < 2; mt++)
#pragma unroll
        for (int nt = 0; nt < 8; nt++) {
            int m = m0 + wm + mt * 16 + gid;
            int n = n0 + wn + nt * 8 + tig * 2;
            float bb0 = bias[n], bb1 = bias[n + 1];
            float2 p0 = make_float2(acc[mt][nt][0] + bb0, acc[mt][nt][1] + bb1);
            float2 p1 = make_float2(acc[mt][nt][2] + bb0, acc[mt][nt][3] + bb1);
            if (!permute) {
                *(float2*)&C[(size_t)m * DD + n] = p0;
                *(float2*)&C[(size_t)(m + 8) * DD + n] = p1;
            } else {
                int h = n >> 6, hd = n & 63;
                int b_ = m >> 11, s = m & 2047;
                *(float2*)&C[(((size_t)(b_ * 16 + h)) * SS + s) * HD + hd] = p0;
                int b2 = (m + 8) >> 11, s2 = (m + 8) & 2047;
                *(float2*)&C[(((size_t)(b2 * 16 + h)) * SS + s2) * HD + hd] = p1;
            }
        }
}

// ---------------------------------------------------------------------------
// Split-BF16 flash attention (m16n8k16) — unchanged from R11 (proven).
// ---------------------------------------------------------------------------
#define KSTR 36
#define VSTR 72

__global__ __launch_bounds__(256, 1)
void flash_mma()
{
    __shared__ u32 sKh[64 * KSTR], sKl[64 * KSTR];
    __shared__ u32 sVh[32 * VSTR], sVl[32 * VSTR];

    int tid = threadIdx.x, wid = tid >> 5, lane = tid & 31;
    int gid = lane >> 2, tig = lane & 3;
    int bh = blockIdx.y, b = bh >> 4, h = bh & 15;
    int qt = (int)gridDim.x - 1 - (int)blockIdx.x;
    int q0 = qt << 7;

    const float* Kbase = g_k + (size_t)bh * SS * HD;
    const float* Vbase = g_v + (size_t)bh * SS * HD;

    int r0 = wid * 16 + gid;
    int grow0 = q0 + r0;

    u32 qh[4][4], ql[4][4];
    {
        const float* q0p = g_q + ((size_t)bh * SS + grow0) * HD;
        const float* q1p = q0p + 8 * HD;
#pragma unroll
        for (int ks = 0; ks < 4; ks++) {
            int c = 16 * ks + 2 * tig;
            float2 f0 = *(const float2*)(q0p + c);
            float2 f1 = *(const float2*)(q1p + c);
            float2 f2 = *(const float2*)(q0p + c + 8);
            float2 f3 = *(const float2*)(q1p + c + 8);
            bsplit(f0.x, f0.y, qh[ks][0], ql[ks][0]);
            bsplit(f1.x, f1.y, qh[ks][1], ql[ks][1]);
            bsplit(f2.x, f2.y, qh[ks][2], ql[ks][2]);
            bsplit(f3.x, f3.y, qh[ks][3], ql[ks][3]);
        }
    }

    float mi0 = -1e30f, mi1 = -1e30f, li0 = 0.0f, li1 = 0.0f;
    float o[8][4];
#pragma unroll
    for (int nt = 0; nt < 8; nt++)
#pragma unroll
        for (int i = 0; i < 4; i++) o[nt][i] = 0.0f;

    int jmax = 2 * qt + 1;
    for (int jt = 0; jt <= jmax; jt++) {
        int j0 = jt << 6;
        __syncthreads();
        {
            int r = tid >> 2, cb = (tid & 3) * 16;
            const float* kp = Kbase + (size_t)(j0 + r) * HD + cb;
            int so = r * KSTR + (cb >> 1);
#pragma unroll
            for (int c4 = 0; c4 < 4; c4++) {
                float4 f = *(const float4*)(kp + c4 * 4);
                u32 h0, l0, h1, l1;
                bsplit(f.x, f.y, h0, l0);
                bsplit(f.z, f.w, h1, l1);
                sts2(sKh + so + c4 * 2, h0, h1);
                sts2(sKl + so + c4 * 2, l0, l1);
            }
            int jp = tid >> 3, hd0 = (tid & 7) * 8;
            const float* vp0 = Vbase + (size_t)(j0 + 2 * jp) * HD + hd0;
            const float* vp1 = vp0 + HD;
            float4 a0 = *(const float4*)(vp0);
            float4 a1 = *(const float4*)(vp0 + 4);
            float4 c0_ = *(const float4*)(vp1);
            float4 c1_ = *(const float4*)(vp1 + 4);
            u32 vh[8], vl[8];
            bsplit(a0.x, c0_.x, vh[0], vl[0]);
            bsplit(a0.y, c0_.y, vh[1], vl[1]);
            bsplit(a0.z, c0_.z, vh[2], vl[2]);
            bsplit(a0.w, c0_.w, vh[3], vl[3]);
            bsplit(a1.x, c1_.x, vh[4], vl[4]);
            bsplit(a1.y, c1_.y, vh[5], vl[5]);
            bsplit(a1.z, c1_.z, vh[6], vl[6]);
            bsplit(a1.w, c1_.w, vh[7], vl[7]);
            int vo = jp * VSTR + hd0;
            sts4(sVh + vo, vh[0], vh[1], vh[2], vh[3]);
            sts4(sVh + vo + 4, vh[4], vh[5], vh[6], vh[7]);
            sts4(sVl + vo, vl[0], vl[1], vl[2], vl[3]);
            sts4(sVl + vo + 4, vl[4], vl[5], vl[6], vl[7]);
        }
        __syncthreads();

        bool active = (j0 <= q0 + wid * 16 + 15);
        if (!active) continue;

        float s[8][4];
#pragma unroll
        for (int nt = 0; nt < 8; nt++)
#pragma unroll
            for (int i = 0; i < 4; i++) s[nt][i] = 0.0f;
#pragma unroll
        for (int ks = 0; ks < 4; ks++) {
#pragma unroll
            for (int nt = 0; nt < 8; nt++) {
                int kr = (nt * 8 + gid) * KSTR + 8 * ks + tig;
                u32 kb[2], kl2[2];
                kb[0]  = sKh[kr];
                kb[1]  = sKh[kr + 4];
                kl2[0] = sKl[kr];
                kl2[1] = sKl[kr + 4];
                mma16(s[nt], qh[ks], kb);
                mma16(s[nt], qh[ks], kl2);
                mma16(s[nt], ql[ks], kb);
            }
        }

        bool applyC = (j0 + 63 > q0 + wid * 16);
        const float* mrow = g_mask + b * SS + j0;
#pragma unroll
        for (int nt = 0; nt < 8; nt++) {
            int cc = nt * 8 + 2 * tig;
            float2 md = *(const float2*)(mrow + cc);
            int gc0 = j0 + cc, gc1 = gc0 + 1;
            float v0 = s[nt][0] * 0.125f + md.x;
            float v1 = s[nt][1] * 0.125f + md.y;
            float v2 = s[nt][2] * 0.125f + md.x;
            float v3 = s[nt][3] * 0.125f + md.y;
            if (applyC) {
                if (gc0 > grow0)     v0 = -1.0e9f;
                if (gc1 > grow0)     v1 = -1.0e9f;
                if (gc0 > grow0 + 8) v2 = -1.0e9f;
                if (gc1 > grow0 + 8) v3 = -1.0e9f;
            }
            s[nt][0] = v0; s[nt][1] = v1; s[nt][2] = v2; s[nt][3] = v3;
        }

        float rm0 = -1e30f, rm1 = -1e30f;
#pragma unroll
        for (int nt = 0; nt < 8; nt++) {
            rm0 = fmaxf(rm0, fmaxf(s[nt][0], s[nt][1]));
            rm1 = fmaxf(rm1, fmaxf(s[nt][2], s[nt][3]));
        }
        rm0 = fmaxf(rm0, __shfl_xor_sync(0xffffffffu, rm0, 1));
        rm0 = fmaxf(rm0, __shfl_xor_sync(0xffffffffu, rm0, 2));
        rm1 = fmaxf(rm1, __shfl_xor_sync(0xffffffffu, rm1, 1));
        rm1 = fmaxf(rm1, __shfl_xor_sync(0xffffffffu, rm1, 2));
        float mn0 = fmaxf(mi0, rm0), mn1 = fmaxf(mi1, rm1);
        float c0 = exp2f((mi0 - mn0) * LOG2E), c1 = exp2f((mi1 - mn1) * LOG2E);
        mi0 = mn0; mi1 = mn1;
        float rs0 = 0.0f, rs1 = 0.0f;
#pragma unroll
        for (int nt = 0; nt < 8; nt++) {
            s[nt][0] = exp2f((s[nt][0] - mn0) * LOG2E);
            s[nt][1] = exp2f((s[nt][1] - mn0) * LOG2E);
            s[nt][2] = exp2f((s[nt][2] - mn1) * LOG2E);
            s[nt][3] = exp2f((s[nt][3] - mn1) * LOG2E);
            rs0 += s[nt][0] + s[nt][1];
            rs1 += s[nt][2] + s[nt][3];
        }
        rs0 += __shfl_xor_sync(0xffffffffu, rs0, 1);
        rs0 += __shfl_xor_sync(0xffffffffu, rs0, 2);
        rs1 += __shfl_xor_sync(0xffffffffu, rs1, 1);
        rs1 += __shfl_xor_sync(0xffffffffu, rs1, 2);
        li0 = li0 * c0 + rs0;
        li1 = li1 * c1 + rs1;
#pragma unroll
        for (int nt = 0; nt < 8; nt++) {
            o[nt][0] *= c0; o[nt][1] *= c0;
            o[nt][2] *= c1; o[nt][3] *= c1;
        }

#pragma unroll
        for (int ks = 0; ks < 4; ks++) {
            u32 ph[4], pl[4];
            bsplit(s[2 * ks][0],     s[2 * ks][1],     ph[0], pl[0]);
            bsplit(s[2 * ks][2],     s[2 * ks][3],     ph[1], pl[1]);
            bsplit(s[2 * ks + 1][0], s[2 * ks + 1][1], ph[2], pl[2]);
            bsplit(s[2 * ks + 1][2], s[2 * ks + 1][3], ph[3], pl[3]);
#pragma unroll
            for (int nt = 0; nt < 8; nt++) {
                int vr = (8 * ks + tig) * VSTR + nt * 8 + gid;
                u32 vb[2], vl2[2];
                vb[0]  = sVh[vr];
                vb[1]  = sVh[vr + 4 * VSTR];
                vl2[0] = sVl[vr];
                vl2[1] = sVl[vr + 4 * VSTR];
                mma16(o[nt], ph, vb);
                mma16(o[nt], pl, vb);
                mma16(o[nt], ph, vl2);
            }
        }
    }

    float i0 = 1.0f / li0, i1 = 1.0f / li1;
#pragma unroll
    for (int nt = 0; nt < 8; nt++) {
        int col = (h << 6) + nt * 8 + 2 * tig;
        *(float2*)&g_attn[(((size_t)(b * SS + grow0)) << 10) + col] =
            make_float2(o[nt][0] * i0, o[nt][1] * i0);
        *(float2*)&g_attn[(((size_t)(b * SS + grow0 + 8)) << 10) + col] =
            make_float2(o[nt][2] * i1, o[nt][3] * i1);
    }
}

// ---------------------------------------------------------------------------
extern "C" void kernel_launch(void* const* d_in, const int* in_sizes, int n_in,
                              void* d_out, int out_size) {
    const float* x  = (const float*)d_in[0];
    const void*  pm = d_in[1];
    const float* Wq = (const float*)d_in[2];
    const float* bq = (const float*)d_in[3];
    const float* Wk = (const float*)d_in[4];
    const float* bk = (const float*)d_in[5];
    const float* Wv = (const float*)d_in[6];
    const float* bv = (const float*)d_in[7];
    const float* Wo = (const float*)d_in[8];
    const float* bo = (const float*)d_in[9];
    float* out = (float*)d_out;

    cudaFuncSetAttribute(gemm_mma, cudaFuncAttributeMaxDynamicSharedMemorySize, GSM_BYTES);

    detect_mask_kernel<<<1, 256>>>((const unsigned char*)pm);
    repack_mask_kernel<<<16, 256>>>(pm);

    dim3 gq(DD / 128, MM / 128, 3);   // (8, 32, 3) fused QKV
    gemm_mma<<<gq, 256, GSM_BYTES>>>(x, Wq, bq, Wk, bk, Wv, bv, nullptr, 0);

    flash_mma<<<dim3(SS / 128, BB * HH), 256>>>();

    dim3 go(DD / 128, MM / 128, 1);
    gemm_mma<<<go, 256, GSM_BYTES>>>(nullptr, Wo, bo, Wo, bo, Wo, bo, out, 1);
}

// round 13
// speedup vs baseline: 1.1302x; 1.1302x over previous
#include <cuda_runtime.h>
#include <cuda_bf16.h>
#include <cstdint>

typedef unsigned int u32;

#define BB 2
#define SS 2048
#define DD 1024
#define HH 16
#define HD 64
#define MM 4096
#define LOG2E 1.4426950408889634f

__device__ float g_q[MM * DD];
__device__ float g_k[MM * DD];
__device__ float g_v[MM * DD];
__device__ float g_attn[MM * DD];
__device__ float g_mask[BB * SS];
__device__ int   g_maskflag;
// pre-split K/V (bf16x2 hi/lo packs), flash-native layouts
__device__ u32 g_kh[MM * DD / 2];   // [bh][s][dpair]
__device__ u32 g_kl[MM * DD / 2];
__device__ u32 g_vh[MM * DD / 2];   // [bh][jpair][n]
__device__ u32 g_vl[MM * DD / 2];

// ---------------------------------------------------------------------------
// Mask detect / repack (proven)
// ---------------------------------------------------------------------------
__global__ void detect_mask_kernel(const unsigned char* __restrict__ p) {
    __shared__ int f1, f23, f4;
    int tid = threadIdx.x;
    if (tid == 0) { f1 = 0; f23 = 0; f4 = 0; }
    __syncthreads();
    int l1 = 0, l23 = 0, l4 = 0;
    for (int i = tid; i < BB * SS; i += blockDim.x) {
        unsigned char v = p[i];
        if (v) {
            int r = i & 3;
            if (r == 1) l1 = 1;
            else if (r == 2 || r == 3) l23 = 1;
            if ((i & 7) == 4) l4 = 1;
        }
    }
    if (l1)  atomicOr(&f1, 1);
    if (l23) atomicOr(&f23, 1);
    if (l4)  atomicOr(&f4, 1);
    __syncthreads();
    if (tid == 0) {
        int flag;
        if (f1) flag = 0;
        else if (f23) flag = 2;
        else if (f4) flag = 1;
        else flag = 3;
        g_maskflag = flag;
    }
}

__global__ void repack_mask_kernel(const void* __restrict__ p) {
    int i = blockIdx.x * blockDim.x + threadIdx.x;
    if (i >= BB * SS) return;
    int flag = g_maskflag;
    bool mv;
    if (flag == 0)      mv = ((const unsigned char*)p)[i] != 0;
    else if (flag == 1) mv = ((const int*)p)[i] != 0;
    else if (flag == 2) mv = ((const float*)p)[i] != 0.0f;
    else                mv = ((const long long*)p)[i] != 0;
    g_mask[i] = mv ? -1.0e9f : 0.0f;
}

// ---------------------------------------------------------------------------
// bf16 helpers
// ---------------------------------------------------------------------------
__device__ __forceinline__ void bsplit(float a, float b, u32& h, u32& l) {
    __nv_bfloat162 hh = __floats2bfloat162_rn(a, b);
    float ra_ = a - __bfloat162float(hh.x);
    float rb_ = b - __bfloat162float(hh.y);
    __nv_bfloat162 ll = __floats2bfloat162_rn(ra_, rb_);
    h = *(u32*)&hh; l = *(u32*)&ll;
}
__device__ __forceinline__ void mma16(float* c, const u32* a, const u32* b) {
    asm volatile("mma.sync.aligned.m16n8k16.row.col.f32.bf16.bf16.f32 "
        "{%0,%1,%2,%3}, {%4,%5,%6,%7}, {%8,%9}, {%0,%1,%2,%3};"
        : "+f"(c[0]), "+f"(c[1]), "+f"(c[2]), "+f"(c[3])
        : "r"(a[0]), "r"(a[1]), "r"(a[2]), "r"(a[3]), "r"(b[0]), "r"(b[1]));
}
__device__ __forceinline__ void sts2(u32* base, u32 a, u32 b) {
    asm volatile("st.shared.v2.b32 [%0], {%1,%2};"
        :: "l"(__cvta_generic_to_shared(base)), "r"(a), "r"(b) : "memory");
}
__device__ __forceinline__ u32 smaddr(const u32* p) {
    return (u32)__cvta_generic_to_shared(p);
}
__device__ __forceinline__ void cpasync16(u32 sdst, const u32* gsrc) {
    asm volatile("cp.async.ca.shared.global [%0], [%1], 16;"
        :: "r"(sdst), "l"(gsrc) : "memory");
}
#define CP_COMMIT() asm volatile("cp.async.commit_group;" ::: "memory")
#define CP_WAIT1()  asm volatile("cp.async.wait_group 1;" ::: "memory")
#define CP_WAIT0()  asm volatile("cp.async.wait_group 0;" ::: "memory")

// ---------------------------------------------------------------------------
// Repack K/V into pre-split bf16 hi/lo packs (flash-native layouts).
// K: pack (k[row][2d], k[row][2d+1])       -> g_kh/g_kl [row][dpair]
// V: pack (v[2jp][n],  v[2jp+1][n])        -> g_vh/g_vl [jp][n]
// ---------------------------------------------------------------------------
__global__ void repack_kv() {
    int i = blockIdx.x * 256 + threadIdx.x;          // 0 .. 2M-1
    {
        int row = i >> 5, dp = i & 31;
        const float* kp = g_k + ((size_t)row << 6) + (dp << 1);
        u32 h, l; bsplit(kp[0], kp[1], h, l);
        g_kh[i] = h; g_kl[i] = l;
    }
    {
        const float* vp = g_v + ((size_t)(i >> 6) << 7) + (i & 63);
        u32 h, l; bsplit(vp[0], vp[64], h, l);
        g_vh[i] = h; g_vl[i] = l;
    }
}

// ---------------------------------------------------------------------------
// Split-BF16 GEMM (NT) — exact R11 version (proven 92us, rel_err 1.09e-5).
// ---------------------------------------------------------------------------
#define SRU 20
#define TU (128 * SRU)

__global__ __launch_bounds__(256, 1)
void gemm_mma(const float* __restrict__ Ain, const float* __restrict__ W,
              const float* __restrict__ bias, float* __restrict__ Cout,
              int srcsel, int dstsel)
{
    __shared__ u32 smAh[TU], smAl[TU], smBh[TU], smBl[TU];

    const float* A = srcsel ? g_attn : Ain;
    float* C = (dstsel == 0) ? Cout : (dstsel == 1 ? g_q : (dstsel == 2 ? g_k : g_v));

    int tid = threadIdx.x, wid = tid >> 5, lane = tid & 31;
    int gid = lane >> 2, tig = lane & 3;
    int m0 = (int)blockIdx.y << 7, n0 = (int)blockIdx.x << 7;
    int wm = (wid & 3) * 32, wn = (wid >> 2) * 64;

    const float* pA = A + (size_t)(m0 + (tid >> 3)) * DD + (tid & 7) * 4;
    const float* pB = W + (size_t)(n0 + (tid >> 3)) * DD + (tid & 7) * 4;
    int sbase = (tid >> 3) * SRU + (tid & 7) * 2;

    float acc[2][8][4];
#pragma unroll
    for (int mt = 0; mt < 2; mt++)
#pragma unroll
        for (int nt = 0; nt < 8; nt++)
#pragma unroll
            for (int i = 0; i < 4; i++) acc[mt][nt][i] = 0.0f;

    float4 ra[4], rb[4];
#pragma unroll
    for (int j = 0; j < 4; j++) {
        ra[j] = *(const float4*)(pA + (size_t)j * 32 * DD);
        rb[j] = *(const float4*)(pB + (size_t)j * 32 * DD);
    }

    const int nk = DD / 32;
    for (int kt = 0; kt < nk; kt++) {
        __syncthreads();
#pragma unroll
        for (int j = 0; j < 4; j++) {
            int off = sbase + j * 32 * SRU;
            u32 h0, l0, h1, l1;
            bsplit(ra[j].x, ra[j].y, h0, l0);
            bsplit(ra[j].z, ra[j].w, h1, l1);
            sts2(smAh + off, h0, h1);
            sts2(smAl + off, l0, l1);
            bsplit(rb[j].x, rb[j].y, h0, l0);
            bsplit(rb[j].z, rb[j].w, h1, l1);
            sts2(smBh + off, h0, h1);
            sts2(smBl + off, l0, l1);
        }
        __syncthreads();
        if (kt + 1 < nk) {
#pragma unroll
            for (int j = 0; j < 4; j++) {
                ra[j] = *(const float4*)(pA + (size_t)j * 32 * DD + (kt + 1) * 32);
                rb[j] = *(const float4*)(pB + (size_t)j * 32 * DD + (kt + 1) * 32);
            }
        }
#pragma unroll
        for (int ks = 0; ks < 2; ks++) {
            int ko = ks * 8;
            u32 ah[2][4], al[2][4];
#pragma unroll
            for (int mt = 0; mt < 2; mt++) {
                int base = (wm + mt * 16 + gid) * SRU + ko + tig;
                ah[mt][0] = smAh[base];
                ah[mt][1] = smAh[base + 8 * SRU];
                ah[mt][2] = smAh[base + 4];
                ah[mt][3] = smAh[base + 8 * SRU + 4];
                al[mt][0] = smAl[base];
                al[mt][1] = smAl[base + 8 * SRU];
                al[mt][2] = smAl[base + 4];
                al[mt][3] = smAl[base + 8 * SRU + 4];
            }
            u32 bh[8][2], bl[8][2];
#pragma unroll
            for (int nt = 0; nt < 8; nt++) {
                int base = (wn + nt * 8 + gid) * SRU + ko + tig;
                bh[nt][0] = smBh[base];
                bh[nt][1] = smBh[base + 4];
                bl[nt][0] = smBl[base];
                bl[nt][1] = smBl[base + 4];
            }
#pragma unroll
            for (int mt = 0; mt < 2; mt++)
#pragma unroll
                for (int nt = 0; nt < 8; nt++) {
                    mma16(acc[mt][nt], ah[mt], bh[nt]);
                    mma16(acc[mt][nt], ah[mt], bl[nt]);
                    mma16(acc[mt][nt], al[mt], bh[nt]);
                }
        }
    }

#pragma unroll
    for (int mt = 0; mt < 2; mt++)
#pragma unroll
        for (int nt = 0; nt < 8; nt++) {
            int m = m0 + wm + mt * 16 + gid;
            int n = n0 + wn + nt * 8 + tig * 2;
            float b0 = bias[n], b1 = bias[n + 1];
            float2 p0 = make_float2(acc[mt][nt][0] + b0, acc[mt][nt][1] + b1);
            float2 p1 = make_float2(acc[mt][nt][2] + b0, acc[mt][nt][3] + b1);
            if (dstsel == 0) {
                *(float2*)&C[(size_t)m * DD + n] = p0;
                *(float2*)&C[(size_t)(m + 8) * DD + n] = p1;
            } else {
                int h = n >> 6, hd = n & 63;
                int b_ = m >> 11, s = m & 2047;
                *(float2*)&C[(((size_t)(b_ * 16 + h)) * SS + s) * HD + hd] = p0;
                int b2 = (m + 8) >> 11, s2 = (m + 8) & 2047;
                *(float2*)&C[(((size_t)(b2 * 16 + h)) * SS + s2) * HD + hd] = p1;
            }
        }
}

// ---------------------------------------------------------------------------
// Split-BF16 flash attention, cp.async double-buffered pre-split K/V.
// CTA: 128 q-rows x one (b,h). 8 warps, warp w -> rows [16w,16w+16).
// Per j-tile: 8x cp.async(16B)/thread fills next buffer while MMAs run.
// ---------------------------------------------------------------------------
#define KSTR 36
#define VSTR 72
#define FBUF 9216                        // u32 per buffer set
#define FSM_BYTES (2 * FBUF * 4)         // 73728

__global__ __launch_bounds__(256, 1)
void flash_mma()
{
    extern __shared__ u32 smd[];

    int tid = threadIdx.x, wid = tid >> 5, lane = tid & 31;
    int gid = lane >> 2, tig = lane & 3;
    int bh = blockIdx.y, b = bh >> 4, h = bh & 15;
    int qt = (int)gridDim.x - 1 - (int)blockIdx.x;   // heavy blocks first
    int q0 = qt << 7;

    const u32* Khb = g_kh + (size_t)bh * SS * 32;
    const u32* Klb = g_kl + (size_t)bh * SS * 32;
    const u32* Vhb = g_vh + (size_t)bh * (SS / 2) * 64;
    const u32* Vlb = g_vl + (size_t)bh * (SS / 2) * 64;

    // per-thread copy coords (2 x 16B chunks per tensor-half)
    int kc0 = tid * 2, kc1 = tid * 2 + 1;
    int kr0 = kc0 >> 3, kcol0 = (kc0 & 7) * 4;
    int kr1 = kc1 >> 3, kcol1 = (kc1 & 7) * 4;
    int vp0 = kc0 >> 4, vcol0 = (kc0 & 15) * 4;
    int vp1 = kc1 >> 4, vcol1 = (kc1 & 15) * 4;

    u32 sb = smaddr(smd);

    int r0 = wid * 16 + gid;
    int grow0 = q0 + r0;

    // Q fragments direct from gmem (fp32 -> hi/lo regs)
    u32 qh[4][4], ql[4][4];
    {
        const float* q0p = g_q + ((size_t)bh * SS + grow0) * HD;
        const float* q1p = q0p + 8 * HD;
#pragma unroll
        for (int ks = 0; ks < 4; ks++) {
            int c = 16 * ks + 2 * tig;
            float2 f0 = *(const float2*)(q0p + c);
            float2 f1 = *(const float2*)(q1p + c);
            float2 f2 = *(const float2*)(q0p + c + 8);
            float2 f3 = *(const float2*)(q1p + c + 8);
            bsplit(f0.x, f0.y, qh[ks][0], ql[ks][0]);
            bsplit(f1.x, f1.y, qh[ks][1], ql[ks][1]);
            bsplit(f2.x, f2.y, qh[ks][2], ql[ks][2]);
            bsplit(f3.x, f3.y, qh[ks][3], ql[ks][3]);
        }
    }

    float mi0 = -1e30f, mi1 = -1e30f, li0 = 0.0f, li1 = 0.0f;
    float o[8][4];
#pragma unroll
    for (int nt = 0; nt < 8; nt++)
#pragma unroll
        for (int i = 0; i < 4; i++) o[nt][i] = 0.0f;

    int jmax = 2 * qt + 1;

    // prologue: tile 0 -> buf 0
    {
        u32 d = sb;
        cpasync16(d + (kr0 * KSTR + kcol0) * 4, Khb + kr0 * 32 + kcol0);
        cpasync16(d + (kr1 * KSTR + kcol1) * 4, Khb + kr1 * 32 + kcol1);
        cpasync16(d + (2304 + kr0 * KSTR + kcol0) * 4, Klb + kr0 * 32 + kcol0);
        cpasync16(d + (2304 + kr1 * KSTR + kcol1) * 4, Klb + kr1 * 32 + kcol1);
        cpasync16(d + (4608 + vp0 * VSTR + vcol0) * 4, Vhb + vp0 * 64 + vcol0);
        cpasync16(d + (4608 + vp1 * VSTR + vcol1) * 4, Vhb + vp1 * 64 + vcol1);
        cpasync16(d + (6912 + vp0 * VSTR + vcol0) * 4, Vlb + vp0 * 64 + vcol0);
        cpasync16(d + (6912 + vp1 * VSTR + vcol1) * 4, Vlb + vp1 * 64 + vcol1);
        CP_COMMIT();
    }

    for (int jt = 0; jt <= jmax; jt++) {
        int cur = jt & 1;
        if (jt + 1 <= jmax) {
            int j1 = (jt + 1) << 6;
            const u32* kh = Khb + j1 * 32;
            const u32* kl = Klb + j1 * 32;
            const u32* vh = Vhb + (j1 >> 1) * 64;
            const u32* vl = Vlb + (j1 >> 1) * 64;
            u32 d = sb + (cur ^ 1) * FBUF * 4;
            cpasync16(d + (kr0 * KSTR + kcol0) * 4, kh + kr0 * 32 + kcol0);
            cpasync16(d + (kr1 * KSTR + kcol1) * 4, kh + kr1 * 32 + kcol1);
            cpasync16(d + (2304 + kr0 * KSTR + kcol0) * 4, kl + kr0 * 32 + kcol0);
            cpasync16(d + (2304 + kr1 * KSTR + kcol1) * 4, kl + kr1 * 32 + kcol1);
            cpasync16(d + (4608 + vp0 * VSTR + vcol0) * 4, vh + vp0 * 64 + vcol0);
            cpasync16(d + (4608 + vp1 * VSTR + vcol1) * 4, vh + vp1 * 64 + vcol1);
            cpasync16(d + (6912 + vp0 * VSTR + vcol0) * 4, vl + vp0 * 64 + vcol0);
            cpasync16(d + (6912 + vp1 * VSTR + vcol1) * 4, vl + vp1 * 64 + vcol1);
            CP_COMMIT();
            CP_WAIT1();
        } else {
            CP_WAIT0();
        }
        __syncthreads();   // tile jt visible to all

        int j0 = jt << 6;
        bool active = (j0 <= q0 + wid * 16 + 15);
        if (active) {
            const u32* sKh = smd + cur * FBUF;
            const u32* sKl = sKh + 2304;
            const u32* sVh = sKh + 4608;
            const u32* sVl = sKh + 6912;

            // S = Q K^T
            float s[8][4];
#pragma unroll
            for (int nt = 0; nt < 8; nt++)
#pragma unroll
                for (int i = 0; i < 4; i++) s[nt][i] = 0.0f;
#pragma unroll
            for (int ks = 0; ks < 4; ks++) {
#pragma unroll
                for (int nt = 0; nt < 8; nt++) {
                    int kr = (nt * 8 + gid) * KSTR + 8 * ks + tig;
                    u32 kb[2], kl2[2];
                    kb[0]  = sKh[kr];
                    kb[1]  = sKh[kr + 4];
                    kl2[0] = sKl[kr];
                    kl2[1] = sKl[kr + 4];
                    mma16(s[nt], qh[ks], kb);
                    mma16(s[nt], qh[ks], kl2);
                    mma16(s[nt], ql[ks], kb);
                }
            }

            // scale + pad mask + causal
            bool applyC = (j0 + 63 > q0 + wid * 16);
            const float* mrow = g_mask + b * SS + j0;
#pragma unroll
            for (int nt = 0; nt < 8; nt++) {
                int cc = nt * 8 + 2 * tig;
                float2 md = *(const float2*)(mrow + cc);
                int gc0 = j0 + cc, gc1 = gc0 + 1;
                float v0 = s[nt][0] * 0.125f + md.x;
                float v1 = s[nt][1] * 0.125f + md.y;
                float v2 = s[nt][2] * 0.125f + md.x;
                float v3 = s[nt][3] * 0.125f + md.y;
                if (applyC) {
                    if (gc0 > grow0)     v0 = -1.0e9f;
                    if (gc1 > grow0)     v1 = -1.0e9f;
                    if (gc0 > grow0 + 8) v2 = -1.0e9f;
                    if (gc1 > grow0 + 8) v3 = -1.0e9f;
                }
                s[nt][0] = v0; s[nt][1] = v1; s[nt][2] = v2; s[nt][3] = v3;
            }

            // online softmax
            float rm0 = -1e30f, rm1 = -1e30f;
#pragma unroll
            for (int nt = 0; nt < 8; nt++) {
                rm0 = fmaxf(rm0, fmaxf(s[nt][0], s[nt][1]));
                rm1 = fmaxf(rm1, fmaxf(s[nt][2], s[nt][3]));
            }
            rm0 = fmaxf(rm0, __shfl_xor_sync(0xffffffffu, rm0, 1));
            rm0 = fmaxf(rm0, __shfl_xor_sync(0xffffffffu, rm0, 2));
            rm1 = fmaxf(rm1, __shfl_xor_sync(0xffffffffu, rm1, 1));
            rm1 = fmaxf(rm1, __shfl_xor_sync(0xffffffffu, rm1, 2));
            float mn0 = fmaxf(mi0, rm0), mn1 = fmaxf(mi1, rm1);
            float c0 = exp2f((mi0 - mn0) * LOG2E), c1 = exp2f((mi1 - mn1) * LOG2E);
            mi0 = mn0; mi1 = mn1;
            float rs0 = 0.0f, rs1 = 0.0f;
#pragma unroll
            for (int nt = 0; nt < 8; nt++) {
                s[nt][0] = exp2f((s[nt][0] - mn0) * LOG2E);
                s[nt][1] = exp2f((s[nt][1] - mn0) * LOG2E);
                s[nt][2] = exp2f((s[nt][2] - mn1) * LOG2E);
                s[nt][3] = exp2f((s[nt][3] - mn1) * LOG2E);
                rs0 += s[nt][0] + s[nt][1];
                rs1 += s[nt][2] + s[nt][3];
            }
            rs0 += __shfl_xor_sync(0xffffffffu, rs0, 1);
            rs0 += __shfl_xor_sync(0xffffffffu, rs0, 2);
            rs1 += __shfl_xor_sync(0xffffffffu, rs1, 1);
            rs1 += __shfl_xor_sync(0xffffffffu, rs1, 2);
            li0 = li0 * c0 + rs0;
            li1 = li1 * c1 + rs1;
#pragma unroll
            for (int nt = 0; nt < 8; nt++) {
                o[nt][0] *= c0; o[nt][1] *= c0;
                o[nt][2] *= c1; o[nt][3] *= c1;
            }

            // O += P V (P direct from C-fragments)
#pragma unroll
            for (int ks = 0; ks < 4; ks++) {
                u32 ph[4], pl[4];
                bsplit(s[2 * ks][0],     s[2 * ks][1],     ph[0], pl[0]);
                bsplit(s[2 * ks][2],     s[2 * ks][3],     ph[1], pl[1]);
                bsplit(s[2 * ks + 1][0], s[2 * ks + 1][1], ph[2], pl[2]);
                bsplit(s[2 * ks + 1][2], s[2 * ks + 1][3], ph[3], pl[3]);
#pragma unroll
                for (int nt = 0; nt < 8; nt++) {
                    int vr = (8 * ks + tig) * VSTR + nt * 8 + gid;
                    u32 vb[2], vl2[2];
                    vb[0]  = sVh[vr];
                    vb[1]  = sVh[vr + 4 * VSTR];
                    vl2[0] = sVl[vr];
                    vl2[1] = sVl[vr + 4 * VSTR];
                    mma16(o[nt], ph, vb);
                    mma16(o[nt], pl, vb);
                    mma16(o[nt], ph, vl2);
                }
            }
        }
        __syncthreads();   // all reads of buf cur done before next iter refills it
    }

    // epilogue
    float i0 = 1.0f / li0, i1 = 1.0f / li1;
#pragma unroll
    for (int nt = 0; nt < 8; nt++) {
        int col = (h << 6) + nt * 8 + 2 * tig;
        *(float2*)&g_attn[(((size_t)(b * SS + grow0)) << 10) + col] =
            make_float2(o[nt][0] * i0, o[nt][1] * i0);
        *(float2*)&g_attn[(((size_t)(b * SS + grow0 + 8)) << 10) + col] =
            make_float2(o[nt][2] * i1, o[nt][3] * i1);
    }
}

// ---------------------------------------------------------------------------
extern "C" void kernel_launch(void* const* d_in, const int* in_sizes, int n_in,
                              void* d_out, int out_size) {
    const float* x  = (const float*)d_in[0];
    const void*  pm = d_in[1];
    const float* Wq = (const float*)d_in[2];
    const float* bq = (const float*)d_in[3];
    const float* Wk = (const float*)d_in[4];
    const float* bk = (const float*)d_in[5];
    const float* Wv = (const float*)d_in[6];
    const float* bv = (const float*)d_in[7];
    const float* Wo = (const float*)d_in[8];
    const float* bo = (const float*)d_in[9];
    float* out = (float*)d_out;

    cudaFuncSetAttribute(flash_mma, cudaFuncAttributeMaxDynamicSharedMemorySize, FSM_BYTES);

    detect_mask_kernel<<<1, 256>>>((const unsigned char*)pm);
    repack_mask_kernel<<<16, 256>>>(pm);

    dim3 gg(DD / 128, MM / 128);   // (8, 32)
    gemm_mma<<<gg, 256>>>(x, Wq, bq, nullptr, 0, 1);
    gemm_mma<<<gg, 256>>>(x, Wk, bk, nullptr, 0, 2);
    gemm_mma<<<gg, 256>>>(x, Wv, bv, nullptr, 0, 3);

    repack_kv<<<8192, 256>>>();

    flash_mma<<<dim3(SS / 128, BB * HH), 256, FSM_BYTES>>>();

    gemm_mma<<<gg, 256>>>(nullptr, Wo, bo, out, 1, 0);
}